// round 3
// baseline (speedup 1.0000x reference)
#include <cuda_runtime.h>
#include <cstdint>

// CorticalSheet fixed-degree SpMM:
//   out[n, b] = sum_k values[n, k] * x[indices[n, k], b] + bias[n]
// N = 1e6, K = 32, B = 8.
//
// Quarter-warp per neuron (8 lanes = 8 output columns), 4 neurons/warp.
// Per synapse the 8 lanes of a group read one 32B row -> exactly 1 L1 wavefront
// per gather (the hardware floor: 32M wavefronts total).
//
// Round-3: __launch_bounds__(256, 4) releases the register budget to 64 so
// ptxas can actually keep 16 gathers in flight (round 2's restructure was
// silently folded back to MLP~4 at 32 regs / 100% occupancy). 32 warps/SM x
// 16 outstanding = 512 loads in flight >> ~250 needed to cover L2-hit latency
// at the 1 wf/cyc L1 demand rate.

static constexpr int K_SYN = 32;
static constexpr int B_COL = 8;

__global__ __launch_bounds__(256, 4)
void cortical_spmm_kernel(const float* __restrict__ x,
                          const float* __restrict__ values,
                          const float* __restrict__ bias,
                          const int*   __restrict__ indices,
                          float* __restrict__ out,
                          int N) {
    const int tid   = blockIdx.x * blockDim.x + threadIdx.x;
    const int warp  = tid >> 5;
    const int lane  = threadIdx.x & 31;
    const int b     = lane & 7;        // output column owned by this lane
    const int gbase = lane & 24;       // first lane of this 8-lane group

    const long n = (long)warp * 4 + (lane >> 3);   // neuron for this group
    const bool active = (n < N);

    // Preload this group's 32 indices + 32 values, 4 per lane (chunk id = b).
    // Warp covers 512B contiguous, 16B/lane. Streaming hint: used once.
    int4   idx4 = make_int4(0, 0, 0, 0);
    float4 val4 = make_float4(0.f, 0.f, 0.f, 0.f);
    float  bi   = 0.f;
    if (active) {
        const size_t base = (size_t)n * K_SYN + (size_t)b * 4;
        idx4 = __ldcs(reinterpret_cast<const int4*>(indices + base));
        val4 = __ldcs(reinterpret_cast<const float4*>(values + base));
        bi   = __ldg(bias + n);
    }

    const float* __restrict__ xb = x + b;

    float a0 = 0.f, a1 = 0.f, a2 = 0.f, a3 = 0.f;

    // Two halves; each half issues 16 independent gathers before any FMA.
    #pragma unroll
    for (int h = 0; h < 2; ++h) {
        float g[16];
        float v[16];

        #pragma unroll
        for (int c = 0; c < 4; ++c) {
            const int src = gbase + h * 4 + c;  // lane holding this int4 chunk
            const int i0 = __shfl_sync(0xffffffffu, idx4.x, src);
            const int i1 = __shfl_sync(0xffffffffu, idx4.y, src);
            const int i2 = __shfl_sync(0xffffffffu, idx4.z, src);
            const int i3 = __shfl_sync(0xffffffffu, idx4.w, src);
            g[c * 4 + 0] = __ldg(xb + (size_t)i0 * B_COL);
            g[c * 4 + 1] = __ldg(xb + (size_t)i1 * B_COL);
            g[c * 4 + 2] = __ldg(xb + (size_t)i2 * B_COL);
            g[c * 4 + 3] = __ldg(xb + (size_t)i3 * B_COL);
        }

        #pragma unroll
        for (int c = 0; c < 4; ++c) {
            const int src = gbase + h * 4 + c;
            v[c * 4 + 0] = __shfl_sync(0xffffffffu, val4.x, src);
            v[c * 4 + 1] = __shfl_sync(0xffffffffu, val4.y, src);
            v[c * 4 + 2] = __shfl_sync(0xffffffffu, val4.z, src);
            v[c * 4 + 3] = __shfl_sync(0xffffffffu, val4.w, src);
        }

        #pragma unroll
        for (int c = 0; c < 4; ++c) {
            a0 = fmaf(v[c * 4 + 0], g[c * 4 + 0], a0);
            a1 = fmaf(v[c * 4 + 1], g[c * 4 + 1], a1);
            a2 = fmaf(v[c * 4 + 2], g[c * 4 + 2], a2);
            a3 = fmaf(v[c * 4 + 3], g[c * 4 + 3], a3);
        }
    }

    if (active) {
        const float acc = (a0 + a1) + (a2 + a3);
        out[(size_t)n * B_COL + b] = acc + bi;
    }
}

extern "C" void kernel_launch(void* const* d_in, const int* in_sizes, int n_in,
                              void* d_out, int out_size) {
    const float* x       = (const float*)d_in[0];
    const float* values  = (const float*)d_in[1];
    const float* bias    = (const float*)d_in[2];
    const int*   indices = (const int*)d_in[3];
    float* out = (float*)d_out;

    const int N = in_sizes[2];            // bias has one element per neuron

    // 4 neurons per warp, 8 warps per block -> 32 neurons per 256-thread block.
    const int neurons_per_block = 32;
    const int grid = (N + neurons_per_block - 1) / neurons_per_block;

    cortical_spmm_kernel<<<grid, 256>>>(x, values, bias, indices, out, N);
}

// round 4
// speedup vs baseline: 1.0924x; 1.0924x over previous
#include <cuda_runtime.h>
#include <cstdint>

// CorticalSheet fixed-degree SpMM:
//   out[n, b] = sum_k values[n, k] * x[indices[n, k], b] + bias[n]
// N = 1e6, K = 32, B = 8.
//
// Quarter-warp per neuron (8 lanes = 8 output columns), 4 neurons/warp.
// Per synapse the 8 lanes of a group read one 32B row -> exactly 1 L1 wavefront
// per gather; 32M wavefronts is the hard floor (~119us).
//
// Round-4: balance occupancy vs MLP. R1 (32 regs, 91% occ, MLP~4) = 232
// outstanding/SM -> L1 93.5%. R3 (64 regs, 45% occ, phased MLP16) = starved
// during drain phases -> L1 84%. This round: launch_bounds(256,6) -> 42-reg
// budget, 48 warps/SM, 8-gather batches -> ~260-290 outstanding > 250 needed.

static constexpr int K_SYN = 32;
static constexpr int B_COL = 8;

__global__ __launch_bounds__(256, 6)
void cortical_spmm_kernel(const float* __restrict__ x,
                          const float* __restrict__ values,
                          const float* __restrict__ bias,
                          const int*   __restrict__ indices,
                          float* __restrict__ out,
                          int N) {
    const int tid   = blockIdx.x * blockDim.x + threadIdx.x;
    const int warp  = tid >> 5;
    const int lane  = threadIdx.x & 31;
    const int b     = lane & 7;        // output column owned by this lane
    const int gbase = lane & 24;       // first lane of this 8-lane group

    const long n = (long)warp * 4 + (lane >> 3);   // neuron for this group
    const bool active = (n < N);

    // Preload this group's 32 indices + 32 values, 4 per lane (chunk id = b).
    // Warp covers 512B contiguous, 16B/lane. Evict-first: used once.
    int4   idx4 = make_int4(0, 0, 0, 0);
    float4 val4 = make_float4(0.f, 0.f, 0.f, 0.f);
    float  bi   = 0.f;
    if (active) {
        const size_t base = (size_t)n * K_SYN + (size_t)b * 4;
        idx4 = __ldcs(reinterpret_cast<const int4*>(indices + base));
        val4 = __ldcs(reinterpret_cast<const float4*>(values + base));
        bi   = __ldg(bias + n);
    }

    const float* __restrict__ xb = x + b;

    float a0 = 0.f, a1 = 0.f, a2 = 0.f, a3 = 0.f;

    // Four phases; each phase issues 8 independent gathers before any FMA.
    #pragma unroll
    for (int p = 0; p < 4; ++p) {
        float g[8];
        float v[8];

        #pragma unroll
        for (int c = 0; c < 2; ++c) {
            const int src = gbase + p * 2 + c;  // lane holding this int4 chunk
            const int i0 = __shfl_sync(0xffffffffu, idx4.x, src);
            const int i1 = __shfl_sync(0xffffffffu, idx4.y, src);
            const int i2 = __shfl_sync(0xffffffffu, idx4.z, src);
            const int i3 = __shfl_sync(0xffffffffu, idx4.w, src);
            g[c * 4 + 0] = __ldg(xb + (size_t)i0 * B_COL);
            g[c * 4 + 1] = __ldg(xb + (size_t)i1 * B_COL);
            g[c * 4 + 2] = __ldg(xb + (size_t)i2 * B_COL);
            g[c * 4 + 3] = __ldg(xb + (size_t)i3 * B_COL);
        }

        #pragma unroll
        for (int c = 0; c < 2; ++c) {
            const int src = gbase + p * 2 + c;
            v[c * 4 + 0] = __shfl_sync(0xffffffffu, val4.x, src);
            v[c * 4 + 1] = __shfl_sync(0xffffffffu, val4.y, src);
            v[c * 4 + 2] = __shfl_sync(0xffffffffu, val4.z, src);
            v[c * 4 + 3] = __shfl_sync(0xffffffffu, val4.w, src);
        }

        #pragma unroll
        for (int c = 0; c < 2; ++c) {
            a0 = fmaf(v[c * 4 + 0], g[c * 4 + 0], a0);
            a1 = fmaf(v[c * 4 + 1], g[c * 4 + 1], a1);
            a2 = fmaf(v[c * 4 + 2], g[c * 4 + 2], a2);
            a3 = fmaf(v[c * 4 + 3], g[c * 4 + 3], a3);
        }
    }

    if (active) {
        const float acc = (a0 + a1) + (a2 + a3);
        out[(size_t)n * B_COL + b] = acc + bi;
    }
}

extern "C" void kernel_launch(void* const* d_in, const int* in_sizes, int n_in,
                              void* d_out, int out_size) {
    const float* x       = (const float*)d_in[0];
    const float* values  = (const float*)d_in[1];
    const float* bias    = (const float*)d_in[2];
    const int*   indices = (const int*)d_in[3];
    float* out = (float*)d_out;

    const int N = in_sizes[2];            // bias has one element per neuron

    // 4 neurons per warp, 8 warps per block -> 32 neurons per 256-thread block.
    const int neurons_per_block = 32;
    const int grid = (N + neurons_per_block - 1) / neurons_per_block;

    cortical_spmm_kernel<<<grid, 256>>>(x, values, bias, indices, out, N);
}

// round 11
// speedup vs baseline: 1.1097x; 1.0158x over previous
#include <cuda_runtime.h>
#include <cstdint>

// CorticalSheet fixed-degree SpMM:
//   out[n, b] = sum_k values[n, k] * x[indices[n, k], b] + bias[n]
// N = 1e6, K = 32, B = 8.
//
// Quarter-warp per neuron (8 lanes = 8 output columns), 4 neurons/warp.
// Per synapse the 8 lanes of a group read one 32B row -> 1 L1 wavefront per
// gather (32M total, the floor). R1/R3/R4 sweep showed occupancy dominates
// per-warp MLP: best = 32 regs @ ~91% occ. This round keeps that exact
// structure and bypasses L1 on the gathers (__ldcg): x is 32MB vs ~200KB L1
// (~0% hit rate), so L1 line fills for gathers are pure pollution that adds
// miss-handling work and evicts the streaming indices/values lines.
//
// (Identical to round-5..10 submissions — none ran: GPU broker timeouts.)

static constexpr int K_SYN = 32;
static constexpr int B_COL = 8;

__global__ __launch_bounds__(256)
void cortical_spmm_kernel(const float* __restrict__ x,
                          const float* __restrict__ values,
                          const float* __restrict__ bias,
                          const int*   __restrict__ indices,
                          float* __restrict__ out,
                          int N) {
    const int tid   = blockIdx.x * blockDim.x + threadIdx.x;
    const int warp  = tid >> 5;
    const int lane  = threadIdx.x & 31;
    const int b     = lane & 7;        // output column owned by this lane
    const int gbase = lane & 24;       // first lane of this 8-lane group

    const long n = (long)warp * 4 + (lane >> 3);   // neuron for this group
    const bool active = (n < N);

    // Preload this group's 32 indices + 32 values, 4 per lane (chunk id = b).
    // Warp covers 512B contiguous, 16B/lane. Default caching: sequential,
    // benefits from L1 now that gathers no longer pollute it.
    int4   idx4 = make_int4(0, 0, 0, 0);
    float4 val4 = make_float4(0.f, 0.f, 0.f, 0.f);
    if (active) {
        const size_t base = (size_t)n * K_SYN + (size_t)b * 4;
        idx4 = *reinterpret_cast<const int4*>(indices + base);
        val4 = *reinterpret_cast<const float4*>(values + base);
    }

    const float* __restrict__ xb = x + b;

    float a0 = 0.f, a1 = 0.f, a2 = 0.f, a3 = 0.f;

    #pragma unroll
    for (int k4 = 0; k4 < 8; ++k4) {
        const int src = gbase + k4;   // lane holding chunk k4 of this neuron
        const int   i0 = __shfl_sync(0xffffffffu, idx4.x, src);
        const int   i1 = __shfl_sync(0xffffffffu, idx4.y, src);
        const int   i2 = __shfl_sync(0xffffffffu, idx4.z, src);
        const int   i3 = __shfl_sync(0xffffffffu, idx4.w, src);
        const float v0 = __shfl_sync(0xffffffffu, val4.x, src);
        const float v1 = __shfl_sync(0xffffffffu, val4.y, src);
        const float v2 = __shfl_sync(0xffffffffu, val4.z, src);
        const float v3 = __shfl_sync(0xffffffffu, val4.w, src);

        // L1-bypass gathers: L2-direct, no dead L1 line fills.
        a0 = fmaf(v0, __ldcg(xb + (size_t)i0 * B_COL), a0);
        a1 = fmaf(v1, __ldcg(xb + (size_t)i1 * B_COL), a1);
        a2 = fmaf(v2, __ldcg(xb + (size_t)i2 * B_COL), a2);
        a3 = fmaf(v3, __ldcg(xb + (size_t)i3 * B_COL), a3);
    }

    if (active) {
        const float acc = (a0 + a1) + (a2 + a3);
        out[(size_t)n * B_COL + b] = acc + __ldg(bias + n);
    }
}

extern "C" void kernel_launch(void* const* d_in, const int* in_sizes, int n_in,
                              void* d_out, int out_size) {
    const float* x       = (const float*)d_in[0];
    const float* values  = (const float*)d_in[1];
    const float* bias    = (const float*)d_in[2];
    const int*   indices = (const int*)d_in[3];
    float* out = (float*)d_out;

    const int N = in_sizes[2];            // bias has one element per neuron

    // 4 neurons per warp, 8 warps per block -> 32 neurons per 256-thread block.
    const int neurons_per_block = 32;
    const int grid = (N + neurons_per_block - 1) / neurons_per_block;

    cortical_spmm_kernel<<<grid, 256>>>(x, values, bias, indices, out, N);
}